// round 14
// baseline (speedup 1.0000x reference)
#include <cuda_runtime.h>
#include <cuda_bf16.h>
#include <cstdint>
#include <math.h>

// ---------------------------------------------------------------------------
// Problem constants: B=4, S=1024, D=768, H=12, hd=64, F=3072, L=6
// ---------------------------------------------------------------------------
#define T_TOK   4096
#define DIM     768
#define QKVDIM  2304
#define FFDIM   3072
#define NLAYER  6
#define NHEAD   12
#define HDIM    64
#define SEQ     1024

// -------------------- scratch buffers (no cudaMalloc allowed) ---------------
__device__ float g_h   [T_TOK * DIM];     // residual stream (fp32, for LN)
__device__ float g_qkv [T_TOK * QKVDIM];  // qkv (fp32, for attention)
__device__ float g_tmp [T_TOK * DIM];     // Wo / FFN2 output (fp32, for LN)
// bf16 hi/lo planes of activations (GEMM A operands)
__device__ __nv_bfloat16 g_hH   [T_TOK * DIM];
__device__ __nv_bfloat16 g_hL   [T_TOK * DIM];
__device__ __nv_bfloat16 g_attnH[T_TOK * DIM];
__device__ __nv_bfloat16 g_attnL[T_TOK * DIM];
__device__ __nv_bfloat16 g_ffnH [T_TOK * FFDIM];
__device__ __nv_bfloat16 g_ffnL [T_TOK * FFDIM];
// transposed + bf16-pre-split weights ([N,K] layout)
__device__ __nv_bfloat16 g_WqkvH[NLAYER * QKVDIM * DIM];
__device__ __nv_bfloat16 g_WqkvL[NLAYER * QKVDIM * DIM];
__device__ __nv_bfloat16 g_WoH  [NLAYER * DIM * DIM];
__device__ __nv_bfloat16 g_WoL  [NLAYER * DIM * DIM];
__device__ __nv_bfloat16 g_W1H  [NLAYER * FFDIM * DIM];
__device__ __nv_bfloat16 g_W1L  [NLAYER * FFDIM * DIM];
__device__ __nv_bfloat16 g_W2H  [NLAYER * DIM * FFDIM];
__device__ __nv_bfloat16 g_W2L  [NLAYER * DIM * FFDIM];

// -------------------- PTX helpers -------------------------------------------
__device__ __forceinline__ uint32_t s2u(const void* p) {
    uint32_t a;
    asm("{ .reg .u64 t; cvta.to.shared.u64 t, %1; cvt.u32.u64 %0, t; }"
        : "=r"(a) : "l"(p));
    return a;
}

#define CP_ASYNC16(dst, src) \
    asm volatile("cp.async.cg.shared.global [%0], [%1], 16;" \
                 :: "r"(dst), "l"(src) : "memory")
#define CP_COMMIT() asm volatile("cp.async.commit_group;" ::: "memory")
#define CP_WAIT0()  asm volatile("cp.async.wait_group 0;" ::: "memory")

__device__ __forceinline__ void ldsm4(uint32_t* r, uint32_t addr) {
    asm volatile("ldmatrix.sync.aligned.m8n8.x4.shared.b16 {%0,%1,%2,%3}, [%4];"
                 : "=r"(r[0]), "=r"(r[1]), "=r"(r[2]), "=r"(r[3]) : "r"(addr));
}

// m16n8k16 bf16 mma: D += A*B, fp32 accumulate
__device__ __forceinline__ void mma16(float* c, const uint32_t* a,
                                      uint32_t b0, uint32_t b1) {
    asm volatile(
        "mma.sync.aligned.m16n8k16.row.col.f32.bf16.bf16.f32 "
        "{%0,%1,%2,%3}, {%4,%5,%6,%7}, {%8,%9}, {%0,%1,%2,%3};"
        : "+f"(c[0]), "+f"(c[1]), "+f"(c[2]), "+f"(c[3])
        : "r"(a[0]), "r"(a[1]), "r"(a[2]), "r"(a[3]), "r"(b0), "r"(b1));
}

__device__ __forceinline__ uint32_t packbf(float x, float y) {
    __nv_bfloat16 bx = __float2bfloat16(x);
    __nv_bfloat16 by = __float2bfloat16(y);
    return ((uint32_t)__bfloat16_as_ushort(by) << 16) |
           (uint32_t)__bfloat16_as_ushort(bx);
}
// split pair (x,y) into packed bf16 hi plane + lo plane
__device__ __forceinline__ void split2(float x, float y,
                                       uint32_t& hi, uint32_t& lo) {
    __nv_bfloat16 hx = __float2bfloat16(x);
    __nv_bfloat16 hy = __float2bfloat16(y);
    hi = ((uint32_t)__bfloat16_as_ushort(hy) << 16) |
         (uint32_t)__bfloat16_as_ushort(hx);
    lo = packbf(x - __bfloat162float(hx), y - __bfloat162float(hy));
}
__device__ __forceinline__ void split1(float x, __nv_bfloat16& hi,
                                       __nv_bfloat16& lo) {
    hi = __float2bfloat16(x);
    lo = __float2bfloat16(x - __bfloat162float(hi));
}

// ---------------------------------------------------------------------------
// bf16x3 tensor-core GEMM: C[M,N] = (Ahi+Alo)[M,K] @ (Whi+Wlo)[N,K]^T + bias.
// All operands pre-split bf16. CTA 128x128, 4 warps (2x2), warp 64x64,
// K-tile 32, double-buffered cp.async, ldmatrix fragment loads.
// smem/stage: AH | AL | BH | BL planes, 128 rows x 40 bf16 (80 B, padded).
// Optional: fp32 C output (skippable), bf16 hi/lo plane output, ReLU.
// ---------------------------------------------------------------------------
#define BSTRB  80                 // bytes per padded smem row (40 bf16)
#define PLANEB (128 * BSTRB)      // 10240 B
#define STAGEB (4 * PLANEB)       // 40960 B
#define GEMM_SMEM_BYTES (2 * STAGEB)   // 81920

__global__ __launch_bounds__(128, 2)
void gemm_bf16x3(const __nv_bfloat16* __restrict__ Ahi,
                 const __nv_bfloat16* __restrict__ Alo,
                 const __nv_bfloat16* __restrict__ Whi,
                 const __nv_bfloat16* __restrict__ Wlo,
                 const float* __restrict__ bias,
                 float* __restrict__ C,
                 __nv_bfloat16* __restrict__ Chi,
                 __nv_bfloat16* __restrict__ Clo,
                 int M, int N, int K, int relu)
{
    extern __shared__ __align__(16) char smc[];
    const uint32_t sb = s2u(smc);
    const int tid  = threadIdx.x;
    const int wid  = tid >> 5;
    const int lane = tid & 31;
    const int gr   = lane >> 2;
    const int tig  = lane & 3;
    const int bn = blockIdx.x;
    const int bm = blockIdx.y;

    const int m0w = (wid >> 1) * 64;
    const int n0w = (wid & 1) * 64;

    // global row pointers (thread t loads row t of each tile)
    const __nv_bfloat16* AHrow = Ahi + ((size_t)bm * 128 + tid) * K;
    const __nv_bfloat16* ALrow = Alo + ((size_t)bm * 128 + tid) * K;
    const __nv_bfloat16* BHrow = Whi + ((size_t)bn * 128 + tid) * K;
    const __nv_bfloat16* BLrow = Wlo + ((size_t)bn * 128 + tid) * K;
    const int nk = K >> 5;

    // ldmatrix per-lane offsets (within plane, bytes)
    const uint32_t aoff = (uint32_t)(m0w + (lane & 7) + ((lane >> 3) & 1) * 8) * BSTRB
                        + ((lane >> 4) & 1) * 16;
    const uint32_t boff = (uint32_t)(n0w + (lane & 7) + ((lane >> 4) & 1) * 8) * BSTRB
                        + ((lane >> 3) & 1) * 16;

    // ---- preload tile 0 ----
    {
        uint32_t d = sb + tid * BSTRB;
        #pragma unroll
        for (int j = 0; j < 4; ++j) CP_ASYNC16(d + j * 16, AHrow + j * 8);
        d += PLANEB;
        #pragma unroll
        for (int j = 0; j < 4; ++j) CP_ASYNC16(d + j * 16, ALrow + j * 8);
        d += PLANEB;
        #pragma unroll
        for (int j = 0; j < 4; ++j) CP_ASYNC16(d + j * 16, BHrow + j * 8);
        d += PLANEB;
        #pragma unroll
        for (int j = 0; j < 4; ++j) CP_ASYNC16(d + j * 16, BLrow + j * 8);
        CP_COMMIT();
    }
    CP_WAIT0();
    __syncthreads();

    float acc[4][8][4];
    #pragma unroll
    for (int mt = 0; mt < 4; ++mt)
        #pragma unroll
        for (int nt = 0; nt < 8; ++nt)
            #pragma unroll
            for (int r = 0; r < 4; ++r)
                acc[mt][nt][r] = 0.f;

    for (int kt = 0; kt < nk; ++kt) {
        const int s = kt & 1;
        const bool more = (kt + 1 < nk);

        if (more) {
            const int ko = (kt + 1) * 32;
            uint32_t d = sb + (s ^ 1) * STAGEB + tid * BSTRB;
            #pragma unroll
            for (int j = 0; j < 4; ++j) CP_ASYNC16(d + j * 16, AHrow + ko + j * 8);
            d += PLANEB;
            #pragma unroll
            for (int j = 0; j < 4; ++j) CP_ASYNC16(d + j * 16, ALrow + ko + j * 8);
            d += PLANEB;
            #pragma unroll
            for (int j = 0; j < 4; ++j) CP_ASYNC16(d + j * 16, BHrow + ko + j * 8);
            d += PLANEB;
            #pragma unroll
            for (int j = 0; j < 4; ++j) CP_ASYNC16(d + j * 16, BLrow + ko + j * 8);
            CP_COMMIT();
        }

        // ---- compute current stage (ldmatrix fragments) ----
        const uint32_t st = sb + s * STAGEB;
        #pragma unroll
        for (int kq = 0; kq < 2; ++kq) {
            uint32_t bh[8][2], bl[8][2];
            #pragma unroll
            for (int p = 0; p < 4; ++p) {
                uint32_t r[4];
                uint32_t ad = st + 2 * PLANEB + boff + p * (16 * BSTRB) + kq * 32;
                ldsm4(r, ad);
                bh[2 * p][0] = r[0]; bh[2 * p][1] = r[1];
                bh[2 * p + 1][0] = r[2]; bh[2 * p + 1][1] = r[3];
                ldsm4(r, ad + PLANEB);
                bl[2 * p][0] = r[0]; bl[2 * p][1] = r[1];
                bl[2 * p + 1][0] = r[2]; bl[2 * p + 1][1] = r[3];
            }
            #pragma unroll
            for (int mt = 0; mt < 4; ++mt) {
                uint32_t ah[4], al[4];
                uint32_t ad = st + aoff + mt * (16 * BSTRB) + kq * 32;
                ldsm4(ah, ad);
                ldsm4(al, ad + PLANEB);
                #pragma unroll
                for (int nt = 0; nt < 8; ++nt) {
                    mma16(acc[mt][nt], ah, bh[nt][0], bh[nt][1]);
                    mma16(acc[mt][nt], ah, bl[nt][0], bl[nt][1]);
                    mma16(acc[mt][nt], al, bh[nt][0], bh[nt][1]);
                }
            }
        }

        if (more) {
            CP_WAIT0();
            __syncthreads();
        }
    }

    // ---- epilogue: bias, opt. ReLU, fp32 and/or bf16-plane stores ----
    #pragma unroll
    for (int nt = 0; nt < 8; ++nt) {
        const int gc = bn * 128 + n0w + nt * 8 + tig * 2;
        float2 bv = *(const float2*)(bias + gc);
        #pragma unroll
        for (int mt = 0; mt < 4; ++mt) {
            const int gm = bm * 128 + m0w + mt * 16 + gr;
            float2 o0 = make_float2(acc[mt][nt][0] + bv.x, acc[mt][nt][1] + bv.y);
            float2 o1 = make_float2(acc[mt][nt][2] + bv.x, acc[mt][nt][3] + bv.y);
            if (relu) {
                o0.x = fmaxf(o0.x, 0.f); o0.y = fmaxf(o0.y, 0.f);
                o1.x = fmaxf(o1.x, 0.f); o1.y = fmaxf(o1.y, 0.f);
            }
            const size_t i0 = (size_t)gm * N + gc;
            const size_t i1 = (size_t)(gm + 8) * N + gc;
            if (C) {
                *(float2*)(C + i0) = o0;
                *(float2*)(C + i1) = o1;
            }
            if (Chi) {
                uint32_t h0, l0, h1, l1;
                split2(o0.x, o0.y, h0, l0);
                split2(o1.x, o1.y, h1, l1);
                ((uint32_t*)Chi)[i0 >> 1] = h0;
                ((uint32_t*)Clo)[i0 >> 1] = l0;
                ((uint32_t*)Chi)[i1 >> 1] = h1;
                ((uint32_t*)Clo)[i1 >> 1] = l1;
            }
        }
    }
}

// ---------------------------------------------------------------------------
// Weight transpose + bf16 hi/lo split: ohi/olo[layer][c][r] = split(in[layer][r][c])
// ---------------------------------------------------------------------------
__global__ __launch_bounds__(256)
void transpose_split(const float* __restrict__ in, __nv_bfloat16* __restrict__ ohi,
                     __nv_bfloat16* __restrict__ olo, int R, int C)
{
    __shared__ float t[32][33];
    const float* ip = in  + (size_t)blockIdx.z * R * C;
    const size_t obase = (size_t)blockIdx.z * R * C;
    const int c0 = blockIdx.x * 32, r0 = blockIdx.y * 32;
    const int x = threadIdx.x, y = threadIdx.y;
    #pragma unroll
    for (int j = 0; j < 32; j += 8)
        t[y + j][x] = ip[(size_t)(r0 + y + j) * C + c0 + x];
    __syncthreads();
    #pragma unroll
    for (int j = 0; j < 32; j += 8) {
        float v = t[x][y + j];
        __nv_bfloat16 hi, lo;
        split1(v, hi, lo);
        size_t idx = obase + (size_t)(c0 + y + j) * R + r0 + x;
        ohi[idx] = hi;
        olo[idx] = lo;
    }
}

// -------------------- packed f32x2 helpers (attention) ----------------------
__device__ __forceinline__ unsigned long long pk2(float x) {
    unsigned long long r;
    asm("mov.b64 %0, {%1, %1};" : "=l"(r) : "f"(x));
    return r;
}
__device__ __forceinline__ void fma2(unsigned long long& c,
                                     unsigned long long a,
                                     unsigned long long b) {
    asm("fma.rn.f32x2 %0, %1, %2, %0;" : "+l"(c) : "l"(a), "l"(b));
}
__device__ __forceinline__ unsigned long long mul2(unsigned long long a,
                                                   unsigned long long b) {
    unsigned long long r;
    asm("mul.rn.f32x2 %0, %1, %2;" : "=l"(r) : "l"(a), "l"(b));
    return r;
}
__device__ __forceinline__ float2 up2(unsigned long long v) {
    float2 f;
    asm("mov.b64 {%0, %1}, %2;" : "=f"(f.x), "=f"(f.y) : "l"(v));
    return f;
}

// ---------------------------------------------------------------------------
// Flash-style attention; now also emits bf16 hi/lo planes of its output.
// ---------------------------------------------------------------------------
__global__ __launch_bounds__(256)
void attn_kernel(const float* __restrict__ qkv,
                 __nv_bfloat16* __restrict__ attnH,
                 __nv_bfloat16* __restrict__ attnL)
{
    __shared__ __align__(16) float qst[64 * 64];
    __shared__ __align__(16) float kp [64 * 64];
    __shared__ __align__(16) float vs [64 * 64];

    const int tid = threadIdx.x;
    const int tx = tid & 15;
    const int ty = tid >> 4;
    const int qt = blockIdx.x;
    const int hh = blockIdx.y;
    const int bb = blockIdx.z;

    const size_t tok0 = (size_t)bb * SEQ;
    const float* qb = qkv + (tok0 + qt * 64) * QKVDIM + hh * HDIM;

    #pragma unroll
    for (int p = 0; p < 4; ++p) {
        int f = tid + p * 256;
        int row = f >> 4;
        int c4 = (f & 15) << 2;
        float4 v = *(const float4*)(qb + (size_t)row * QKVDIM + c4);
        qst[(c4 + 0) * 64 + row] = v.x;
        qst[(c4 + 1) * 64 + row] = v.y;
        qst[(c4 + 2) * 64 + row] = v.z;
        qst[(c4 + 3) * 64 + row] = v.w;
    }

    float m[4], l[4];
    unsigned long long op[4][2];
    #pragma unroll
    for (int i = 0; i < 4; ++i) {
        m[i] = -1e30f; l[i] = 0.f;
        op[i][0] = 0ULL; op[i][1] = 0ULL;
    }

    for (int kt = 0; kt < 16; ++kt) {
        const float* kb = qkv + (tok0 + kt * 64) * QKVDIM + DIM + hh * HDIM;
        const float* vb = kb + DIM;

        __syncthreads();
        #pragma unroll
        for (int p = 0; p < 4; ++p) {
            int f = tid + p * 256;
            int row = f >> 4;
            int c4 = (f & 15) << 2;
            float4 kv = *(const float4*)(kb + (size_t)row * QKVDIM + c4);
            kp[(c4 + 0) * 64 + row] = kv.x;
            kp[(c4 + 1) * 64 + row] = kv.y;
            kp[(c4 + 2) * 64 + row] = kv.z;
            kp[(c4 + 3) * 64 + row] = kv.w;
            float4 vv = *(const float4*)(vb + (size_t)row * QKVDIM + c4);
            *(float4*)&vs[row * 64 + c4] = vv;
        }
        __syncthreads();

        unsigned long long sp[4][2];
        #pragma unroll
        for (int i = 0; i < 4; ++i) { sp[i][0] = 0ULL; sp[i][1] = 0ULL; }

        #pragma unroll 4
        for (int d = 0; d < 64; ++d) {
            float4 a = *(const float4*)&qst[d * 64 + ty * 4];
            ulonglong2 b = *(const ulonglong2*)&kp[d * 64 + tx * 4];
            unsigned long long ap0 = pk2(a.x), ap1 = pk2(a.y);
            unsigned long long ap2 = pk2(a.z), ap3 = pk2(a.w);
            fma2(sp[0][0], ap0, b.x); fma2(sp[0][1], ap0, b.y);
            fma2(sp[1][0], ap1, b.x); fma2(sp[1][1], ap1, b.y);
            fma2(sp[2][0], ap2, b.x); fma2(sp[2][1], ap2, b.y);
            fma2(sp[3][0], ap3, b.x); fma2(sp[3][1], ap3, b.y);
        }

        float s[4][4];
        #pragma unroll
        for (int i = 0; i < 4; ++i) {
            float2 t0 = up2(sp[i][0]);
            float2 t1 = up2(sp[i][1]);
            s[i][0] = t0.x * 0.125f;
            s[i][1] = t0.y * 0.125f;
            s[i][2] = t1.x * 0.125f;
            s[i][3] = t1.y * 0.125f;
        }

        float pv4[4][4];
        #pragma unroll
        for (int i = 0; i < 4; ++i) {
            float mt = fmaxf(fmaxf(s[i][0], s[i][1]), fmaxf(s[i][2], s[i][3]));
            #pragma unroll
            for (int off = 8; off > 0; off >>= 1)
                mt = fmaxf(mt, __shfl_xor_sync(0xffffffffu, mt, off));
            float mn = fmaxf(m[i], mt);
            float lsum = 0.f;
            #pragma unroll
            for (int j = 0; j < 4; ++j) {
                pv4[i][j] = __expf(s[i][j] - mn);
                lsum += pv4[i][j];
            }
            #pragma unroll
            for (int off = 8; off > 0; off >>= 1)
                lsum += __shfl_xor_sync(0xffffffffu, lsum, off);
            float alpha = __expf(m[i] - mn);
            l[i] = l[i] * alpha + lsum;
            m[i] = mn;
            unsigned long long ap = pk2(alpha);
            op[i][0] = mul2(op[i][0], ap);
            op[i][1] = mul2(op[i][1], ap);
        }

        __syncthreads();
        #pragma unroll
        for (int i = 0; i < 4; ++i)
            *(float4*)&kp[(ty * 4 + i) * 64 + tx * 4] =
                make_float4(pv4[i][0], pv4[i][1], pv4[i][2], pv4[i][3]);
        __syncthreads();

        #pragma unroll 2
        for (int kk4 = 0; kk4 < 64; kk4 += 4) {
            float4 a4[4];
            #pragma unroll
            for (int i = 0; i < 4; ++i)
                a4[i] = *(const float4*)&kp[(ty * 4 + i) * 64 + kk4];
            #pragma unroll
            for (int u = 0; u < 4; ++u) {
                ulonglong2 b = *(const ulonglong2*)&vs[(kk4 + u) * 64 + tx * 4];
                #pragma unroll
                for (int i = 0; i < 4; ++i) {
                    float av = (u == 0) ? a4[i].x : (u == 1) ? a4[i].y
                             : (u == 2) ? a4[i].z : a4[i].w;
                    unsigned long long ap = pk2(av);
                    fma2(op[i][0], ap, b.x);
                    fma2(op[i][1], ap, b.y);
                }
            }
        }
    }

    const size_t orow0 = tok0 + qt * 64;
    #pragma unroll
    for (int i = 0; i < 4; ++i) {
        float inv = 1.0f / l[i];
        float2 c0 = up2(op[i][0]);
        float2 c1 = up2(op[i][1]);
        float4 r = make_float4(c0.x * inv, c0.y * inv, c1.x * inv, c1.y * inv);
        size_t ei = (orow0 + ty * 4 + i) * DIM + hh * HDIM + tx * 4;
        uint32_t h0, l0, h1, l1;
        split2(r.x, r.y, h0, l0);
        split2(r.z, r.w, h1, l1);
        *(uint2*)((uint32_t*)attnH + (ei >> 1)) = make_uint2(h0, h1);
        *(uint2*)((uint32_t*)attnL + (ei >> 1)) = make_uint2(l0, l1);
    }
}

// ---------------------------------------------------------------------------
// Fused residual + LayerNorm; optionally emits bf16 hi/lo planes.
// ---------------------------------------------------------------------------
__device__ __forceinline__ float block_sum256(float x, float* red)
{
    #pragma unroll
    for (int off = 16; off > 0; off >>= 1)
        x += __shfl_down_sync(0xffffffffu, x, off);
    if ((threadIdx.x & 31) == 0) red[threadIdx.x >> 5] = x;
    __syncthreads();
    float r = red[0] + red[1] + red[2] + red[3] +
              red[4] + red[5] + red[6] + red[7];
    __syncthreads();
    return r;
}

__global__ __launch_bounds__(256)
void ln_kernel(const float* __restrict__ h, const float* __restrict__ delta,
               const float* __restrict__ g, const float* __restrict__ b,
               float* __restrict__ out,
               __nv_bfloat16* __restrict__ outH,
               __nv_bfloat16* __restrict__ outL)
{
    __shared__ float red[8];
    const int row = blockIdx.x;
    const int tid = threadIdx.x;
    const size_t base = (size_t)row * DIM;

    float v[3];
    #pragma unroll
    for (int j = 0; j < 3; ++j) {
        int idx = tid + j * 256;
        float x = h[base + idx];
        if (delta) x += delta[base + idx];
        v[j] = x;
    }
    float mu = block_sum256(v[0] + v[1] + v[2], red) * (1.0f / 768.0f);
    float d0 = v[0] - mu, d1 = v[1] - mu, d2 = v[2] - mu;
    float var = block_sum256(d0 * d0 + d1 * d1 + d2 * d2, red) * (1.0f / 768.0f);
    float rs = rsqrtf(var + 1e-5f);

    float dd[3] = { d0, d1, d2 };
    #pragma unroll
    for (int j = 0; j < 3; ++j) {
        int idx = tid + j * 256;
        float o = dd[j] * rs * g[idx] + b[idx];
        out[base + idx] = o;
        if (outH) {
            __nv_bfloat16 hi, lo;
            split1(o, hi, lo);
            outH[base + idx] = hi;
            outL[base + idx] = lo;
        }
    }
}

// ---------------------------------------------------------------------------
// Positional encoding add: h = x + PE (fp32 + bf16 planes).
// ---------------------------------------------------------------------------
__global__ __launch_bounds__(256)
void posenc_kernel(const float* __restrict__ x, float* __restrict__ h,
                   __nv_bfloat16* __restrict__ hH,
                   __nv_bfloat16* __restrict__ hL)
{
    const int token = blockIdx.x;
    const int s = token & (SEQ - 1);
    #pragma unroll
    for (int j = 0; j < 3; ++j) {
        int d = threadIdx.x + j * 256;
        int i2 = d >> 1;
        float div = expf((float)(2 * i2) * (-9.210340371976184f / 768.0f));
        float ang = (float)s * div;
        float pe = (d & 1) ? cosf(ang) : sinf(ang);
        size_t idx = (size_t)token * DIM + d;
        float val = x[idx] + pe;
        h[idx] = val;
        __nv_bfloat16 hi, lo;
        split1(val, hi, lo);
        hH[idx] = hi;
        hL[idx] = lo;
    }
}

// ---------------------------------------------------------------------------
// kernel_launch
// ---------------------------------------------------------------------------
extern "C" void kernel_launch(void* const* d_in, const int* in_sizes, int n_in,
                              void* d_out, int out_size)
{
    (void)in_sizes; (void)n_in; (void)out_size;

    const float* x    = (const float*)d_in[0];
    const float* Wqkv = (const float*)d_in[1];
    const float* bqkv = (const float*)d_in[2];
    const float* Wo   = (const float*)d_in[3];
    const float* bo   = (const float*)d_in[4];
    const float* ln1g = (const float*)d_in[5];
    const float* ln1b = (const float*)d_in[6];
    const float* W1   = (const float*)d_in[7];
    const float* b1   = (const float*)d_in[8];
    const float* W2   = (const float*)d_in[9];
    const float* b2   = (const float*)d_in[10];
    const float* ln2g = (const float*)d_in[11];
    const float* ln2b = (const float*)d_in[12];
    const float* lnfg = (const float*)d_in[13];
    const float* lnfb = (const float*)d_in[14];
    float* out = (float*)d_out;

    float *h, *qkvb, *tmpb;
    __nv_bfloat16 *hH, *hL, *attnH, *attnL, *ffnH, *ffnL;
    __nv_bfloat16 *WqkvH, *WqkvL, *WoH, *WoL, *W1H, *W1L, *W2H, *W2L;
    cudaGetSymbolAddress((void**)&h,     g_h);
    cudaGetSymbolAddress((void**)&qkvb,  g_qkv);
    cudaGetSymbolAddress((void**)&tmpb,  g_tmp);
    cudaGetSymbolAddress((void**)&hH,    g_hH);
    cudaGetSymbolAddress((void**)&hL,    g_hL);
    cudaGetSymbolAddress((void**)&attnH, g_attnH);
    cudaGetSymbolAddress((void**)&attnL, g_attnL);
    cudaGetSymbolAddress((void**)&ffnH,  g_ffnH);
    cudaGetSymbolAddress((void**)&ffnL,  g_ffnL);
    cudaGetSymbolAddress((void**)&WqkvH, g_WqkvH);
    cudaGetSymbolAddress((void**)&WqkvL, g_WqkvL);
    cudaGetSymbolAddress((void**)&WoH,   g_WoH);
    cudaGetSymbolAddress((void**)&WoL,   g_WoL);
    cudaGetSymbolAddress((void**)&W1H,   g_W1H);
    cudaGetSymbolAddress((void**)&W1L,   g_W1L);
    cudaGetSymbolAddress((void**)&W2H,   g_W2H);
    cudaGetSymbolAddress((void**)&W2L,   g_W2L);

    cudaFuncSetAttribute(gemm_bf16x3,
                         cudaFuncAttributeMaxDynamicSharedMemorySize,
                         GEMM_SMEM_BYTES);

    // weight transpose + bf16 pre-split: W[K,N] -> Whi/Wlo[N,K]
    dim3 tb(32, 8);
    transpose_split<<<dim3(QKVDIM / 32, DIM / 32, NLAYER), tb>>>(Wqkv, WqkvH, WqkvL, DIM, QKVDIM);
    transpose_split<<<dim3(DIM / 32, DIM / 32, NLAYER), tb>>>(Wo, WoH, WoL, DIM, DIM);
    transpose_split<<<dim3(FFDIM / 32, DIM / 32, NLAYER), tb>>>(W1, W1H, W1L, DIM, FFDIM);
    transpose_split<<<dim3(DIM / 32, FFDIM / 32, NLAYER), tb>>>(W2, W2H, W2L, FFDIM, DIM);

    posenc_kernel<<<T_TOK, 256>>>(x, h, hH, hL);

    for (int l = 0; l < NLAYER; ++l) {
        // QKV projection: fp32 output for attention
        gemm_bf16x3<<<dim3(QKVDIM / 128, T_TOK / 128), 128, GEMM_SMEM_BYTES>>>(
            hH, hL, WqkvH + (size_t)l * QKVDIM * DIM, WqkvL + (size_t)l * QKVDIM * DIM,
            bqkv + (size_t)l * QKVDIM, qkvb, nullptr, nullptr,
            T_TOK, QKVDIM, DIM, 0);

        attn_kernel<<<dim3(SEQ / 64, NHEAD, 4), 256>>>(qkvb, attnH, attnL);

        // output projection: fp32 for LN residual
        gemm_bf16x3<<<dim3(DIM / 128, T_TOK / 128), 128, GEMM_SMEM_BYTES>>>(
            attnH, attnL, WoH + (size_t)l * DIM * DIM, WoL + (size_t)l * DIM * DIM,
            bo + (size_t)l * DIM, tmpb, nullptr, nullptr,
            T_TOK, DIM, DIM, 0);

        ln_kernel<<<T_TOK, 256>>>(h, tmpb, ln1g + (size_t)l * DIM,
                                  ln1b + (size_t)l * DIM, h, hH, hL);

        // FFN up + ReLU: planes only (fp32 output unused)
        gemm_bf16x3<<<dim3(FFDIM / 128, T_TOK / 128), 128, GEMM_SMEM_BYTES>>>(
            hH, hL, W1H + (size_t)l * FFDIM * DIM, W1L + (size_t)l * FFDIM * DIM,
            b1 + (size_t)l * FFDIM, nullptr, ffnH, ffnL,
            T_TOK, FFDIM, DIM, 1);

        // FFN down: fp32 for LN residual
        gemm_bf16x3<<<dim3(DIM / 128, T_TOK / 128), 128, GEMM_SMEM_BYTES>>>(
            ffnH, ffnL, W2H + (size_t)l * DIM * FFDIM, W2L + (size_t)l * DIM * FFDIM,
            b2 + (size_t)l * DIM, tmpb, nullptr, nullptr,
            T_TOK, DIM, FFDIM, 0);

        ln_kernel<<<T_TOK, 256>>>(h, tmpb, ln2g + (size_t)l * DIM,
                                  ln2b + (size_t)l * DIM, h, hH, hL);
    }

    ln_kernel<<<T_TOK, 256>>>(h, nullptr, lnfg, lnfb, out, nullptr, nullptr);
}

// round 15
// speedup vs baseline: 1.1499x; 1.1499x over previous
#include <cuda_runtime.h>
#include <cuda_bf16.h>
#include <cstdint>
#include <math.h>

// ---------------------------------------------------------------------------
// Problem constants: B=4, S=1024, D=768, H=12, hd=64, F=3072, L=6
// ---------------------------------------------------------------------------
#define T_TOK   4096
#define DIM     768
#define QKVDIM  2304
#define FFDIM   3072
#define NLAYER  6
#define NHEAD   12
#define HDIM    64
#define SEQ     1024

// -------------------- scratch buffers (no cudaMalloc allowed) ---------------
__device__ float g_h   [T_TOK * DIM];     // residual stream (fp32, for LN)
__device__ float g_qkv [T_TOK * QKVDIM];  // qkv (fp32, for attention)
__device__ float g_tmp [T_TOK * DIM];     // Wo / FFN2 output (fp32, for LN)
// bf16 hi/lo planes of activations (GEMM A operands)
__device__ __nv_bfloat16 g_hH   [T_TOK * DIM];
__device__ __nv_bfloat16 g_hL   [T_TOK * DIM];
__device__ __nv_bfloat16 g_attnH[T_TOK * DIM];
__device__ __nv_bfloat16 g_attnL[T_TOK * DIM];
__device__ __nv_bfloat16 g_ffnH [T_TOK * FFDIM];
__device__ __nv_bfloat16 g_ffnL [T_TOK * FFDIM];
// transposed + bf16-pre-split weights ([N,K] layout)
__device__ __nv_bfloat16 g_WqkvH[NLAYER * QKVDIM * DIM];
__device__ __nv_bfloat16 g_WqkvL[NLAYER * QKVDIM * DIM];
__device__ __nv_bfloat16 g_WoH  [NLAYER * DIM * DIM];
__device__ __nv_bfloat16 g_WoL  [NLAYER * DIM * DIM];
__device__ __nv_bfloat16 g_W1H  [NLAYER * FFDIM * DIM];
__device__ __nv_bfloat16 g_W1L  [NLAYER * FFDIM * DIM];
__device__ __nv_bfloat16 g_W2H  [NLAYER * DIM * FFDIM];
__device__ __nv_bfloat16 g_W2L  [NLAYER * DIM * FFDIM];

// -------------------- PTX helpers -------------------------------------------
__device__ __forceinline__ uint32_t s2u(const void* p) {
    uint32_t a;
    asm("{ .reg .u64 t; cvta.to.shared.u64 t, %1; cvt.u32.u64 %0, t; }"
        : "=r"(a) : "l"(p));
    return a;
}

#define CP_ASYNC16(dst, src) \
    asm volatile("cp.async.cg.shared.global [%0], [%1], 16;" \
                 :: "r"(dst), "l"(src) : "memory")
#define CP_COMMIT() asm volatile("cp.async.commit_group;" ::: "memory")
#define CP_WAIT0()  asm volatile("cp.async.wait_group 0;" ::: "memory")

__device__ __forceinline__ void ldsm4(uint32_t* r, uint32_t addr) {
    asm volatile("ldmatrix.sync.aligned.m8n8.x4.shared.b16 {%0,%1,%2,%3}, [%4];"
                 : "=r"(r[0]), "=r"(r[1]), "=r"(r[2]), "=r"(r[3]) : "r"(addr));
}

// m16n8k16 bf16 mma: D += A*B, fp32 accumulate
__device__ __forceinline__ void mma16(float* c, const uint32_t* a,
                                      uint32_t b0, uint32_t b1) {
    asm volatile(
        "mma.sync.aligned.m16n8k16.row.col.f32.bf16.bf16.f32 "
        "{%0,%1,%2,%3}, {%4,%5,%6,%7}, {%8,%9}, {%0,%1,%2,%3};"
        : "+f"(c[0]), "+f"(c[1]), "+f"(c[2]), "+f"(c[3])
        : "r"(a[0]), "r"(a[1]), "r"(a[2]), "r"(a[3]), "r"(b0), "r"(b1));
}

__device__ __forceinline__ uint32_t packbf(float x, float y) {
    __nv_bfloat16 bx = __float2bfloat16(x);
    __nv_bfloat16 by = __float2bfloat16(y);
    return ((uint32_t)__bfloat16_as_ushort(by) << 16) |
           (uint32_t)__bfloat16_as_ushort(bx);
}
// split pair (x,y) into packed bf16 hi plane + lo plane
__device__ __forceinline__ void split2(float x, float y,
                                       uint32_t& hi, uint32_t& lo) {
    __nv_bfloat16 hx = __float2bfloat16(x);
    __nv_bfloat16 hy = __float2bfloat16(y);
    hi = ((uint32_t)__bfloat16_as_ushort(hy) << 16) |
         (uint32_t)__bfloat16_as_ushort(hx);
    lo = packbf(x - __bfloat162float(hx), y - __bfloat162float(hy));
}
__device__ __forceinline__ void split1(float x, __nv_bfloat16& hi,
                                       __nv_bfloat16& lo) {
    hi = __float2bfloat16(x);
    lo = __float2bfloat16(x - __bfloat162float(hi));
}

// ---------------------------------------------------------------------------
// bf16x3 tensor-core GEMM: C[M,N] = (Ahi+Alo)[M,K] @ (Whi+Wlo)[N,K]^T + bias.
// CTA 128x128, 256 threads / 8 warps (4m x 2n), warp tile 32x64, K-tile 32,
// double-buffered cp.async, ldmatrix fragments. 2 CTAs/SM -> 4 warps/SMSP.
// mma passes ordered hh -> hl -> lh across mt/nt for long independence chains.
// smem/stage: AH | AL | BH | BL planes, 128 rows x 40 bf16 (80 B, padded).
// ---------------------------------------------------------------------------
#define BSTRB  80                 // bytes per padded smem row (40 bf16)
#define PLANEB (128 * BSTRB)      // 10240 B
#define STAGEB (4 * PLANEB)       // 40960 B
#define GEMM_SMEM_BYTES (2 * STAGEB)   // 81920

__global__ __launch_bounds__(256, 2)
void gemm_bf16x3(const __nv_bfloat16* __restrict__ Ahi,
                 const __nv_bfloat16* __restrict__ Alo,
                 const __nv_bfloat16* __restrict__ Whi,
                 const __nv_bfloat16* __restrict__ Wlo,
                 const float* __restrict__ bias,
                 float* __restrict__ C,
                 __nv_bfloat16* __restrict__ Chi,
                 __nv_bfloat16* __restrict__ Clo,
                 int M, int N, int K, int relu)
{
    extern __shared__ __align__(16) char smc[];
    const uint32_t sb = s2u(smc);
    const int tid  = threadIdx.x;
    const int wid  = tid >> 5;
    const int lane = tid & 31;
    const int gr   = lane >> 2;
    const int tig  = lane & 3;
    const int bn = blockIdx.x;
    const int bm = blockIdx.y;

    const int m0w = (wid >> 1) * 32;   // 4 m-warps of 32 rows
    const int n0w = (wid & 1) * 64;    // 2 n-warps of 64 cols

    // loader: 2 threads per row, 32B each
    const int lrow = tid >> 1;
    const int lco  = (tid & 1) * 16;   // bf16 element offset within 32-elem row
    const __nv_bfloat16* AHrow = Ahi + ((size_t)bm * 128 + lrow) * K + lco;
    const __nv_bfloat16* ALrow = Alo + ((size_t)bm * 128 + lrow) * K + lco;
    const __nv_bfloat16* BHrow = Whi + ((size_t)bn * 128 + lrow) * K + lco;
    const __nv_bfloat16* BLrow = Wlo + ((size_t)bn * 128 + lrow) * K + lco;
    const uint32_t dbase = (uint32_t)lrow * BSTRB + (uint32_t)(tid & 1) * 32;
    const int nk = K >> 5;

    // ldmatrix per-lane offsets (within plane, bytes)
    const uint32_t aoff = (uint32_t)(m0w + (lane & 7) + ((lane >> 3) & 1) * 8) * BSTRB
                        + ((lane >> 4) & 1) * 16;
    const uint32_t boff = (uint32_t)(n0w + (lane & 7) + ((lane >> 4) & 1) * 8) * BSTRB
                        + ((lane >> 3) & 1) * 16;

    // ---- preload tile 0 ----
    {
        uint32_t d = sb + dbase;
        CP_ASYNC16(d, AHrow);               CP_ASYNC16(d + 16, AHrow + 8);
        d += PLANEB;
        CP_ASYNC16(d, ALrow);               CP_ASYNC16(d + 16, ALrow + 8);
        d += PLANEB;
        CP_ASYNC16(d, BHrow);               CP_ASYNC16(d + 16, BHrow + 8);
        d += PLANEB;
        CP_ASYNC16(d, BLrow);               CP_ASYNC16(d + 16, BLrow + 8);
        CP_COMMIT();
    }
    CP_WAIT0();
    __syncthreads();

    float acc[2][8][4];
    #pragma unroll
    for (int mt = 0; mt < 2; ++mt)
        #pragma unroll
        for (int nt = 0; nt < 8; ++nt)
            #pragma unroll
            for (int r = 0; r < 4; ++r)
                acc[mt][nt][r] = 0.f;

    for (int kt = 0; kt < nk; ++kt) {
        const int s = kt & 1;
        const bool more = (kt + 1 < nk);

        if (more) {
            const int ko = (kt + 1) * 32;
            uint32_t d = sb + (s ^ 1) * STAGEB + dbase;
            CP_ASYNC16(d, AHrow + ko);      CP_ASYNC16(d + 16, AHrow + ko + 8);
            d += PLANEB;
            CP_ASYNC16(d, ALrow + ko);      CP_ASYNC16(d + 16, ALrow + ko + 8);
            d += PLANEB;
            CP_ASYNC16(d, BHrow + ko);      CP_ASYNC16(d + 16, BHrow + ko + 8);
            d += PLANEB;
            CP_ASYNC16(d, BLrow + ko);      CP_ASYNC16(d + 16, BLrow + ko + 8);
            CP_COMMIT();
        }

        const uint32_t st = sb + s * STAGEB;
        #pragma unroll
        for (int kq = 0; kq < 2; ++kq) {
            // A fragments for both m-tiles (hi/lo), reused across n-halves
            uint32_t ah[2][4], al[2][4];
            #pragma unroll
            for (int mt = 0; mt < 2; ++mt) {
                uint32_t ad = st + aoff + mt * (16 * BSTRB) + kq * 32;
                ldsm4(ah[mt], ad);
                ldsm4(al[mt], ad + PLANEB);
            }
            #pragma unroll
            for (int nh = 0; nh < 2; ++nh) {
                uint32_t bh[4][2], bl[4][2];
                #pragma unroll
                for (int p = 0; p < 2; ++p) {
                    uint32_t r[4];
                    uint32_t ad = st + 2 * PLANEB + boff
                                + (nh * 2 + p) * (16 * BSTRB) + kq * 32;
                    ldsm4(r, ad);
                    bh[2 * p][0] = r[0]; bh[2 * p][1] = r[1];
                    bh[2 * p + 1][0] = r[2]; bh[2 * p + 1][1] = r[3];
                    ldsm4(r, ad + PLANEB);
                    bl[2 * p][0] = r[0]; bl[2 * p][1] = r[1];
                    bl[2 * p + 1][0] = r[2]; bl[2 * p + 1][1] = r[3];
                }
                // pass 1: hi*hi (8 independent mmas)
                #pragma unroll
                for (int mt = 0; mt < 2; ++mt)
                    #pragma unroll
                    for (int j = 0; j < 4; ++j)
                        mma16(acc[mt][nh * 4 + j], ah[mt], bh[j][0], bh[j][1]);
                // pass 2: hi*lo
                #pragma unroll
                for (int mt = 0; mt < 2; ++mt)
                    #pragma unroll
                    for (int j = 0; j < 4; ++j)
                        mma16(acc[mt][nh * 4 + j], ah[mt], bl[j][0], bl[j][1]);
                // pass 3: lo*hi
                #pragma unroll
                for (int mt = 0; mt < 2; ++mt)
                    #pragma unroll
                    for (int j = 0; j < 4; ++j)
                        mma16(acc[mt][nh * 4 + j], al[mt], bh[j][0], bh[j][1]);
            }
        }

        if (more) {
            CP_WAIT0();
            __syncthreads();
        }
    }

    // ---- epilogue: bias, opt. ReLU, fp32 and/or bf16-plane stores ----
    #pragma unroll
    for (int nt = 0; nt < 8; ++nt) {
        const int gc = bn * 128 + n0w + nt * 8 + tig * 2;
        float2 bv = *(const float2*)(bias + gc);
        #pragma unroll
        for (int mt = 0; mt < 2; ++mt) {
            const int gm = bm * 128 + m0w + mt * 16 + gr;
            float2 o0 = make_float2(acc[mt][nt][0] + bv.x, acc[mt][nt][1] + bv.y);
            float2 o1 = make_float2(acc[mt][nt][2] + bv.x, acc[mt][nt][3] + bv.y);
            if (relu) {
                o0.x = fmaxf(o0.x, 0.f); o0.y = fmaxf(o0.y, 0.f);
                o1.x = fmaxf(o1.x, 0.f); o1.y = fmaxf(o1.y, 0.f);
            }
            const size_t i0 = (size_t)gm * N + gc;
            const size_t i1 = (size_t)(gm + 8) * N + gc;
            if (C) {
                *(float2*)(C + i0) = o0;
                *(float2*)(C + i1) = o1;
            }
            if (Chi) {
                uint32_t h0, l0, h1, l1;
                split2(o0.x, o0.y, h0, l0);
                split2(o1.x, o1.y, h1, l1);
                ((uint32_t*)Chi)[i0 >> 1] = h0;
                ((uint32_t*)Clo)[i0 >> 1] = l0;
                ((uint32_t*)Chi)[i1 >> 1] = h1;
                ((uint32_t*)Clo)[i1 >> 1] = l1;
            }
        }
    }
}

// ---------------------------------------------------------------------------
// Weight transpose + bf16 hi/lo split.
// ---------------------------------------------------------------------------
__global__ __launch_bounds__(256)
void transpose_split(const float* __restrict__ in, __nv_bfloat16* __restrict__ ohi,
                     __nv_bfloat16* __restrict__ olo, int R, int C)
{
    __shared__ float t[32][33];
    const float* ip = in  + (size_t)blockIdx.z * R * C;
    const size_t obase = (size_t)blockIdx.z * R * C;
    const int c0 = blockIdx.x * 32, r0 = blockIdx.y * 32;
    const int x = threadIdx.x, y = threadIdx.y;
    #pragma unroll
    for (int j = 0; j < 32; j += 8)
        t[y + j][x] = ip[(size_t)(r0 + y + j) * C + c0 + x];
    __syncthreads();
    #pragma unroll
    for (int j = 0; j < 32; j += 8) {
        float v = t[x][y + j];
        __nv_bfloat16 hi, lo;
        split1(v, hi, lo);
        size_t idx = obase + (size_t)(c0 + y + j) * R + r0 + x;
        ohi[idx] = hi;
        olo[idx] = lo;
    }
}

// -------------------- packed f32x2 helpers (attention) ----------------------
__device__ __forceinline__ unsigned long long pk2(float x) {
    unsigned long long r;
    asm("mov.b64 %0, {%1, %1};" : "=l"(r) : "f"(x));
    return r;
}
__device__ __forceinline__ void fma2(unsigned long long& c,
                                     unsigned long long a,
                                     unsigned long long b) {
    asm("fma.rn.f32x2 %0, %1, %2, %0;" : "+l"(c) : "l"(a), "l"(b));
}
__device__ __forceinline__ unsigned long long mul2(unsigned long long a,
                                                   unsigned long long b) {
    unsigned long long r;
    asm("mul.rn.f32x2 %0, %1, %2;" : "=l"(r) : "l"(a), "l"(b));
    return r;
}
__device__ __forceinline__ float2 up2(unsigned long long v) {
    float2 f;
    asm("mov.b64 {%0, %1}, %2;" : "=f"(f.x), "=f"(f.y) : "l"(v));
    return f;
}

// ---------------------------------------------------------------------------
// Flash-style attention; emits bf16 hi/lo planes of its output.
// ---------------------------------------------------------------------------
__global__ __launch_bounds__(256)
void attn_kernel(const float* __restrict__ qkv,
                 __nv_bfloat16* __restrict__ attnH,
                 __nv_bfloat16* __restrict__ attnL)
{
    __shared__ __align__(16) float qst[64 * 64];
    __shared__ __align__(16) float kp [64 * 64];
    __shared__ __align__(16) float vs [64 * 64];

    const int tid = threadIdx.x;
    const int tx = tid & 15;
    const int ty = tid >> 4;
    const int qt = blockIdx.x;
    const int hh = blockIdx.y;
    const int bb = blockIdx.z;

    const size_t tok0 = (size_t)bb * SEQ;
    const float* qb = qkv + (tok0 + qt * 64) * QKVDIM + hh * HDIM;

    #pragma unroll
    for (int p = 0; p < 4; ++p) {
        int f = tid + p * 256;
        int row = f >> 4;
        int c4 = (f & 15) << 2;
        float4 v = *(const float4*)(qb + (size_t)row * QKVDIM + c4);
        qst[(c4 + 0) * 64 + row] = v.x;
        qst[(c4 + 1) * 64 + row] = v.y;
        qst[(c4 + 2) * 64 + row] = v.z;
        qst[(c4 + 3) * 64 + row] = v.w;
    }

    float m[4], l[4];
    unsigned long long op[4][2];
    #pragma unroll
    for (int i = 0; i < 4; ++i) {
        m[i] = -1e30f; l[i] = 0.f;
        op[i][0] = 0ULL; op[i][1] = 0ULL;
    }

    for (int kt = 0; kt < 16; ++kt) {
        const float* kb = qkv + (tok0 + kt * 64) * QKVDIM + DIM + hh * HDIM;
        const float* vb = kb + DIM;

        __syncthreads();
        #pragma unroll
        for (int p = 0; p < 4; ++p) {
            int f = tid + p * 256;
            int row = f >> 4;
            int c4 = (f & 15) << 2;
            float4 kv = *(const float4*)(kb + (size_t)row * QKVDIM + c4);
            kp[(c4 + 0) * 64 + row] = kv.x;
            kp[(c4 + 1) * 64 + row] = kv.y;
            kp[(c4 + 2) * 64 + row] = kv.z;
            kp[(c4 + 3) * 64 + row] = kv.w;
            float4 vv = *(const float4*)(vb + (size_t)row * QKVDIM + c4);
            *(float4*)&vs[row * 64 + c4] = vv;
        }
        __syncthreads();

        unsigned long long sp[4][2];
        #pragma unroll
        for (int i = 0; i < 4; ++i) { sp[i][0] = 0ULL; sp[i][1] = 0ULL; }

        #pragma unroll 4
        for (int d = 0; d < 64; ++d) {
            float4 a = *(const float4*)&qst[d * 64 + ty * 4];
            ulonglong2 b = *(const ulonglong2*)&kp[d * 64 + tx * 4];
            unsigned long long ap0 = pk2(a.x), ap1 = pk2(a.y);
            unsigned long long ap2 = pk2(a.z), ap3 = pk2(a.w);
            fma2(sp[0][0], ap0, b.x); fma2(sp[0][1], ap0, b.y);
            fma2(sp[1][0], ap1, b.x); fma2(sp[1][1], ap1, b.y);
            fma2(sp[2][0], ap2, b.x); fma2(sp[2][1], ap2, b.y);
            fma2(sp[3][0], ap3, b.x); fma2(sp[3][1], ap3, b.y);
        }

        float s[4][4];
        #pragma unroll
        for (int i = 0; i < 4; ++i) {
            float2 t0 = up2(sp[i][0]);
            float2 t1 = up2(sp[i][1]);
            s[i][0] = t0.x * 0.125f;
            s[i][1] = t0.y * 0.125f;
            s[i][2] = t1.x * 0.125f;
            s[i][3] = t1.y * 0.125f;
        }

        float pv4[4][4];
        #pragma unroll
        for (int i = 0; i < 4; ++i) {
            float mt = fmaxf(fmaxf(s[i][0], s[i][1]), fmaxf(s[i][2], s[i][3]));
            #pragma unroll
            for (int off = 8; off > 0; off >>= 1)
                mt = fmaxf(mt, __shfl_xor_sync(0xffffffffu, mt, off));
            float mn = fmaxf(m[i], mt);
            float lsum = 0.f;
            #pragma unroll
            for (int j = 0; j < 4; ++j) {
                pv4[i][j] = __expf(s[i][j] - mn);
                lsum += pv4[i][j];
            }
            #pragma unroll
            for (int off = 8; off > 0; off >>= 1)
                lsum += __shfl_xor_sync(0xffffffffu, lsum, off);
            float alpha = __expf(m[i] - mn);
            l[i] = l[i] * alpha + lsum;
            m[i] = mn;
            unsigned long long ap = pk2(alpha);
            op[i][0] = mul2(op[i][0], ap);
            op[i][1] = mul2(op[i][1], ap);
        }

        __syncthreads();
        #pragma unroll
        for (int i = 0; i < 4; ++i)
            *(float4*)&kp[(ty * 4 + i) * 64 + tx * 4] =
                make_float4(pv4[i][0], pv4[i][1], pv4[i][2], pv4[i][3]);
        __syncthreads();

        #pragma unroll 2
        for (int kk4 = 0; kk4 < 64; kk4 += 4) {
            float4 a4[4];
            #pragma unroll
            for (int i = 0; i < 4; ++i)
                a4[i] = *(const float4*)&kp[(ty * 4 + i) * 64 + kk4];
            #pragma unroll
            for (int u = 0; u < 4; ++u) {
                ulonglong2 b = *(const ulonglong2*)&vs[(kk4 + u) * 64 + tx * 4];
                #pragma unroll
                for (int i = 0; i < 4; ++i) {
                    float av = (u == 0) ? a4[i].x : (u == 1) ? a4[i].y
                             : (u == 2) ? a4[i].z : a4[i].w;
                    unsigned long long ap = pk2(av);
                    fma2(op[i][0], ap, b.x);
                    fma2(op[i][1], ap, b.y);
                }
            }
        }
    }

    const size_t orow0 = tok0 + qt * 64;
    #pragma unroll
    for (int i = 0; i < 4; ++i) {
        float inv = 1.0f / l[i];
        float2 c0 = up2(op[i][0]);
        float2 c1 = up2(op[i][1]);
        float4 r = make_float4(c0.x * inv, c0.y * inv, c1.x * inv, c1.y * inv);
        size_t ei = (orow0 + ty * 4 + i) * DIM + hh * HDIM + tx * 4;
        uint32_t h0, l0, h1, l1;
        split2(r.x, r.y, h0, l0);
        split2(r.z, r.w, h1, l1);
        *(uint2*)((uint32_t*)attnH + (ei >> 1)) = make_uint2(h0, h1);
        *(uint2*)((uint32_t*)attnL + (ei >> 1)) = make_uint2(l0, l1);
    }
}

// ---------------------------------------------------------------------------
// Fused residual + LayerNorm; optionally emits bf16 hi/lo planes.
// ---------------------------------------------------------------------------
__device__ __forceinline__ float block_sum256(float x, float* red)
{
    #pragma unroll
    for (int off = 16; off > 0; off >>= 1)
        x += __shfl_down_sync(0xffffffffu, x, off);
    if ((threadIdx.x & 31) == 0) red[threadIdx.x >> 5] = x;
    __syncthreads();
    float r = red[0] + red[1] + red[2] + red[3] +
              red[4] + red[5] + red[6] + red[7];
    __syncthreads();
    return r;
}

__global__ __launch_bounds__(256)
void ln_kernel(const float* __restrict__ h, const float* __restrict__ delta,
               const float* __restrict__ g, const float* __restrict__ b,
               float* __restrict__ out,
               __nv_bfloat16* __restrict__ outH,
               __nv_bfloat16* __restrict__ outL)
{
    __shared__ float red[8];
    const int row = blockIdx.x;
    const int tid = threadIdx.x;
    const size_t base = (size_t)row * DIM;

    float v[3];
    #pragma unroll
    for (int j = 0; j < 3; ++j) {
        int idx = tid + j * 256;
        float x = h[base + idx];
        if (delta) x += delta[base + idx];
        v[j] = x;
    }
    float mu = block_sum256(v[0] + v[1] + v[2], red) * (1.0f / 768.0f);
    float d0 = v[0] - mu, d1 = v[1] - mu, d2 = v[2] - mu;
    float var = block_sum256(d0 * d0 + d1 * d1 + d2 * d2, red) * (1.0f / 768.0f);
    float rs = rsqrtf(var + 1e-5f);

    float dd[3] = { d0, d1, d2 };
    #pragma unroll
    for (int j = 0; j < 3; ++j) {
        int idx = tid + j * 256;
        float o = dd[j] * rs * g[idx] + b[idx];
        out[base + idx] = o;
        if (outH) {
            __nv_bfloat16 hi, lo;
            split1(o, hi, lo);
            outH[base + idx] = hi;
            outL[base + idx] = lo;
        }
    }
}

// ---------------------------------------------------------------------------
// Positional encoding add: h = x + PE (fp32 + bf16 planes).
// ---------------------------------------------------------------------------
__global__ __launch_bounds__(256)
void posenc_kernel(const float* __restrict__ x, float* __restrict__ h,
                   __nv_bfloat16* __restrict__ hH,
                   __nv_bfloat16* __restrict__ hL)
{
    const int token = blockIdx.x;
    const int s = token & (SEQ - 1);
    #pragma unroll
    for (int j = 0; j < 3; ++j) {
        int d = threadIdx.x + j * 256;
        int i2 = d >> 1;
        float div = expf((float)(2 * i2) * (-9.210340371976184f / 768.0f));
        float ang = (float)s * div;
        float pe = (d & 1) ? cosf(ang) : sinf(ang);
        size_t idx = (size_t)token * DIM + d;
        float val = x[idx] + pe;
        h[idx] = val;
        __nv_bfloat16 hi, lo;
        split1(val, hi, lo);
        hH[idx] = hi;
        hL[idx] = lo;
    }
}

// ---------------------------------------------------------------------------
// kernel_launch
// ---------------------------------------------------------------------------
extern "C" void kernel_launch(void* const* d_in, const int* in_sizes, int n_in,
                              void* d_out, int out_size)
{
    (void)in_sizes; (void)n_in; (void)out_size;

    const float* x    = (const float*)d_in[0];
    const float* Wqkv = (const float*)d_in[1];
    const float* bqkv = (const float*)d_in[2];
    const float* Wo   = (const float*)d_in[3];
    const float* bo   = (const float*)d_in[4];
    const float* ln1g = (const float*)d_in[5];
    const float* ln1b = (const float*)d_in[6];
    const float* W1   = (const float*)d_in[7];
    const float* b1   = (const float*)d_in[8];
    const float* W2   = (const float*)d_in[9];
    const float* b2   = (const float*)d_in[10];
    const float* ln2g = (const float*)d_in[11];
    const float* ln2b = (const float*)d_in[12];
    const float* lnfg = (const float*)d_in[13];
    const float* lnfb = (const float*)d_in[14];
    float* out = (float*)d_out;

    float *h, *qkvb, *tmpb;
    __nv_bfloat16 *hH, *hL, *attnH, *attnL, *ffnH, *ffnL;
    __nv_bfloat16 *WqkvH, *WqkvL, *WoH, *WoL, *W1H, *W1L, *W2H, *W2L;
    cudaGetSymbolAddress((void**)&h,     g_h);
    cudaGetSymbolAddress((void**)&qkvb,  g_qkv);
    cudaGetSymbolAddress((void**)&tmpb,  g_tmp);
    cudaGetSymbolAddress((void**)&hH,    g_hH);
    cudaGetSymbolAddress((void**)&hL,    g_hL);
    cudaGetSymbolAddress((void**)&attnH, g_attnH);
    cudaGetSymbolAddress((void**)&attnL, g_attnL);
    cudaGetSymbolAddress((void**)&ffnH,  g_ffnH);
    cudaGetSymbolAddress((void**)&ffnL,  g_ffnL);
    cudaGetSymbolAddress((void**)&WqkvH, g_WqkvH);
    cudaGetSymbolAddress((void**)&WqkvL, g_WqkvL);
    cudaGetSymbolAddress((void**)&WoH,   g_WoH);
    cudaGetSymbolAddress((void**)&WoL,   g_WoL);
    cudaGetSymbolAddress((void**)&W1H,   g_W1H);
    cudaGetSymbolAddress((void**)&W1L,   g_W1L);
    cudaGetSymbolAddress((void**)&W2H,   g_W2H);
    cudaGetSymbolAddress((void**)&W2L,   g_W2L);

    cudaFuncSetAttribute(gemm_bf16x3,
                         cudaFuncAttributeMaxDynamicSharedMemorySize,
                         GEMM_SMEM_BYTES);

    // weight transpose + bf16 pre-split: W[K,N] -> Whi/Wlo[N,K]
    dim3 tb(32, 8);
    transpose_split<<<dim3(QKVDIM / 32, DIM / 32, NLAYER), tb>>>(Wqkv, WqkvH, WqkvL, DIM, QKVDIM);
    transpose_split<<<dim3(DIM / 32, DIM / 32, NLAYER), tb>>>(Wo, WoH, WoL, DIM, DIM);
    transpose_split<<<dim3(FFDIM / 32, DIM / 32, NLAYER), tb>>>(W1, W1H, W1L, DIM, FFDIM);
    transpose_split<<<dim3(DIM / 32, FFDIM / 32, NLAYER), tb>>>(W2, W2H, W2L, FFDIM, DIM);

    posenc_kernel<<<T_TOK, 256>>>(x, h, hH, hL);

    for (int l = 0; l < NLAYER; ++l) {
        // QKV projection: fp32 output for attention
        gemm_bf16x3<<<dim3(QKVDIM / 128, T_TOK / 128), 256, GEMM_SMEM_BYTES>>>(
            hH, hL, WqkvH + (size_t)l * QKVDIM * DIM, WqkvL + (size_t)l * QKVDIM * DIM,
            bqkv + (size_t)l * QKVDIM, qkvb, nullptr, nullptr,
            T_TOK, QKVDIM, DIM, 0);

        attn_kernel<<<dim3(SEQ / 64, NHEAD, 4), 256>>>(qkvb, attnH, attnL);

        // output projection: fp32 for LN residual
        gemm_bf16x3<<<dim3(DIM / 128, T_TOK / 128), 256, GEMM_SMEM_BYTES>>>(
            attnH, attnL, WoH + (size_t)l * DIM * DIM, WoL + (size_t)l * DIM * DIM,
            bo + (size_t)l * DIM, tmpb, nullptr, nullptr,
            T_TOK, DIM, DIM, 0);

        ln_kernel<<<T_TOK, 256>>>(h, tmpb, ln1g + (size_t)l * DIM,
                                  ln1b + (size_t)l * DIM, h, hH, hL);

        // FFN up + ReLU: planes only (fp32 output unused)
        gemm_bf16x3<<<dim3(FFDIM / 128, T_TOK / 128), 256, GEMM_SMEM_BYTES>>>(
            hH, hL, W1H + (size_t)l * FFDIM * DIM, W1L + (size_t)l * FFDIM * DIM,
            b1 + (size_t)l * FFDIM, nullptr, ffnH, ffnL,
            T_TOK, FFDIM, DIM, 1);

        // FFN down: fp32 for LN residual
        gemm_bf16x3<<<dim3(DIM / 128, T_TOK / 128), 256, GEMM_SMEM_BYTES>>>(
            ffnH, ffnL, W2H + (size_t)l * DIM * FFDIM, W2L + (size_t)l * DIM * FFDIM,
            b2 + (size_t)l * DIM, tmpb, nullptr, nullptr,
            T_TOK, DIM, FFDIM, 0);

        ln_kernel<<<T_TOK, 256>>>(h, tmpb, ln2g + (size_t)l * DIM,
                                  ln2b + (size_t)l * DIM, h, hH, hL);
    }

    ln_kernel<<<T_TOK, 256>>>(h, nullptr, lnfg, lnfb, out, nullptr, nullptr);
}